// round 5
// baseline (speedup 1.0000x reference)
#include <cuda_runtime.h>
#include <stdint.h>

// QuantizationLayer: out[i, 4j + k] = bit (3-k) of rint(x[i,j]*16 - 0.5), as f32.
// Steady-state regime: input L2-resident across graph replays (cacheable loads),
// output evict-first (__stcs). GRID=1024 -> exactly 4 tiles/CTA, all co-resident.
// Software pipeline: prefetch next tile's 8 loads before the current store burst.

#define TPB 256
#define UNROLL 8
#define TILE (TPB * UNROLL)   // 2048 elements per block-tile
#define GRID 1024             // 4096 tiles / 1024 = exactly 4 tiles per CTA

__device__ __forceinline__ void quant_store(float v, float4* out4, int i)
{
    // Match JAX exactly: two separate f32 ops, round-half-even.
    float t = v * 16.0f;
    t = t - 0.5f;
    int num = (int)rintf(t);
    num &= 255;  // uint8 wraparound emulation (no-op for x in [0,1))

    float4 bits;
    bits.x = (num & 8) ? 1.0f : 0.0f;
    bits.y = (num & 4) ? 1.0f : 0.0f;
    bits.z = (num & 2) ? 1.0f : 0.0f;
    bits.w = (num & 1) ? 1.0f : 0.0f;
    __stcs(out4 + i, bits);
}

__global__ void __launch_bounds__(TPB)
quant_bits_kernel(const float* __restrict__ x, float* __restrict__ out, int n)
{
    float4* out4 = reinterpret_cast<float4*>(out);
    const int n_tiles = (n + TILE - 1) / TILE;

    int tile = blockIdx.x;
    if (tile >= n_tiles) return;

    // Prologue: load first tile (8 independent cacheable loads, MLP=8).
    float v[UNROLL];
    int base = tile * TILE + threadIdx.x;
    bool full = (base + (UNROLL - 1) * TPB < n);
#pragma unroll
    for (int u = 0; u < UNROLL; u++) {
        int i = base + u * TPB;
        v[u] = (full || i < n) ? x[i] : 0.0f;
    }

    while (true) {
        int next_tile = tile + GRID;
        float vn[UNROLL];
        bool have_next = (next_tile < n_tiles);
        int nbase = next_tile * TILE + threadIdx.x;

        // Prefetch next tile BEFORE the store burst: loads stay in flight
        // while the stores of the current tile drain.
        if (have_next) {
            bool nfull = (nbase + (UNROLL - 1) * TPB < n);
#pragma unroll
            for (int u = 0; u < UNROLL; u++) {
                int i = nbase + u * TPB;
                vn[u] = (nfull || i < n) ? x[i] : 0.0f;
            }
        }

        // Process + store current tile.
        if (full) {
#pragma unroll
            for (int u = 0; u < UNROLL; u++)
                quant_store(v[u], out4, base + u * TPB);
        } else {
#pragma unroll
            for (int u = 0; u < UNROLL; u++) {
                int i = base + u * TPB;
                if (i < n) quant_store(v[u], out4, i);
            }
        }

        if (!have_next) break;
        tile = next_tile;
        base = nbase;
        full = (base + (UNROLL - 1) * TPB < n);
#pragma unroll
        for (int u = 0; u < UNROLL; u++)
            v[u] = vn[u];
    }
}

extern "C" void kernel_launch(void* const* d_in, const int* in_sizes, int n_in,
                              void* d_out, int out_size)
{
    const float* x = (const float*)d_in[0];
    float* out = (float*)d_out;
    int n = in_sizes[0];   // 4096 * 2048 = 8388608

    quant_bits_kernel<<<GRID, TPB>>>(x, out, n);
}

// round 6
// speedup vs baseline: 1.0589x; 1.0589x over previous
#include <cuda_runtime.h>
#include <stdint.h>

// QuantizationLayer: out[i, 4j + k] = bit (3-k) of rint(x[i,j]*16 - 0.5), as f32.
// Combination of the two proven-best attributes:
//  - R2 shape: one-shot grid, UNROLL=4, low regs -> occ ~82% (best measured)
//  - R4 policy: cacheable input (L2-resident across graph replays) + __stcs output
// No pipeline, no grid-stride loop (both measured neutral-to-negative).

#define TPB 256
#define UNROLL 4

__global__ void __launch_bounds__(TPB, 8)
quant_bits_kernel(const float* __restrict__ x, float* __restrict__ out, int n)
{
    int base = blockIdx.x * (TPB * UNROLL) + threadIdx.x;
    float4* out4 = reinterpret_cast<float4*>(out);

    // Front-batched independent cacheable loads (L2-resident across replays).
    float v[UNROLL];
#pragma unroll
    for (int u = 0; u < UNROLL; u++) {
        int i = base + u * TPB;
        v[u] = (i < n) ? x[i] : 0.0f;
    }

#pragma unroll
    for (int u = 0; u < UNROLL; u++) {
        int i = base + u * TPB;
        if (i >= n) continue;

        // Match JAX exactly: two separate f32 ops, round-half-even.
        float t = v[u] * 16.0f;
        t = t - 0.5f;
        int num = (int)rintf(t);
        num &= 255;  // uint8 wraparound emulation (no-op for x in [0,1))

        float4 bits;
        bits.x = (num & 8) ? 1.0f : 0.0f;
        bits.y = (num & 4) ? 1.0f : 0.0f;
        bits.z = (num & 2) ? 1.0f : 0.0f;
        bits.w = (num & 1) ? 1.0f : 0.0f;
        __stcs(out4 + i, bits);   // evict-first: don't displace L2-resident input
    }
}

extern "C" void kernel_launch(void* const* d_in, const int* in_sizes, int n_in,
                              void* d_out, int out_size)
{
    const float* x = (const float*)d_in[0];
    float* out = (float*)d_out;
    int n = in_sizes[0];   // 4096 * 2048 = 8388608

    int blocks = (n + TPB * UNROLL - 1) / (TPB * UNROLL);
    quant_bits_kernel<<<blocks, TPB>>>(x, out, n);
}